// round 3
// baseline (speedup 1.0000x reference)
#include <cuda_runtime.h>
#include <math.h>

// Problem constants
#define Bv 4
#define Sv 2048
#define Dv 1024
#define Ev 8
#define Hv 2048
#define Tv (Bv*Sv)        // 8192 tokens
#define Av (2*Tv)         // 16384 assignments (top_k = 2)

// GEMM tiling
#define BM 128
#define BN 64
#define BK 16

// Device scratch (static allocations; no cudaMalloc allowed)
__device__ int   g_count[Ev];
__device__ int   g_list[Ev*Tv];           // assignment ids per expert
__device__ int   g_exp[Av];               // expert per assignment
__device__ float g_w[Av];                 // combine weight per assignment
__device__ float g_h[(size_t)Av*Hv];      // gelu(FFN1) activations, 134 MB
__device__ float g_y[(size_t)Av*Dv];      // weighted FFN2 outputs, 67 MB

__global__ void k_zero() {
    if (threadIdx.x < Ev) g_count[threadIdx.x] = 0;
}

// Gating: one warp per token. logits = x @ Wg + bg; top-2; normalized weights.
__global__ void k_gate(const float* __restrict__ x,
                       const float* __restrict__ Wg,
                       const float* __restrict__ bg) {
    int warp = threadIdx.x >> 5, lane = threadIdx.x & 31;
    int t = blockIdx.x * 8 + warp;
    if (t >= Tv) return;
    float acc[Ev];
#pragma unroll
    for (int e = 0; e < Ev; e++) acc[e] = 0.f;
    const float* xr = x + (size_t)t * Dv;
    for (int d = lane; d < Dv; d += 32) {
        float xv = xr[d];
        const float* wr = Wg + d * Ev;
#pragma unroll
        for (int e = 0; e < Ev; e++) acc[e] += xv * __ldg(wr + e);
    }
#pragma unroll
    for (int e = 0; e < Ev; e++) {
#pragma unroll
        for (int o = 16; o > 0; o >>= 1)
            acc[e] += __shfl_xor_sync(0xffffffffu, acc[e], o);
    }
    if (lane == 0) {
        float l[Ev];
#pragma unroll
        for (int e = 0; e < Ev; e++) l[e] = acc[e] + bg[e];
        int e0 = 0;
#pragma unroll
        for (int e = 1; e < Ev; e++) if (l[e] > l[e0]) e0 = e;
        int e1 = (e0 == 0) ? 1 : 0;
#pragma unroll
        for (int e = 0; e < Ev; e++) if (e != e0 && l[e] > l[e1]) e1 = e;
        float w0 = 1.f / (1.f + expf(l[e1] - l[e0]));
        float w1 = 1.f - w0;
        int a0 = 2 * t, a1 = 2 * t + 1;
        g_exp[a0] = e0; g_exp[a1] = e1;
        g_w[a0] = w0;   g_w[a1] = w1;
        int s0 = atomicAdd(&g_count[e0], 1); g_list[e0 * Tv + s0] = a0;
        int s1 = atomicAdd(&g_count[e1], 1); g_list[e1 * Tv + s1] = a1;
    }
}

__device__ __forceinline__ float gelu_tanh(float v) {
    float u = 0.7978845608028654f * (v + 0.044715f * v * v * v);
    float th;
    asm("tanh.approx.f32 %0, %1;" : "=f"(th) : "f"(u));
    return 0.5f * v * (1.f + th);
}

// FFN1: h[a, :] = gelu(x[tok(a), :] @ W1[e] + b1[e]) for a in expert e's list
__global__ __launch_bounds__(256) void k_ffn1(const float* __restrict__ x,
                                              const float* __restrict__ W1,
                                              const float* __restrict__ b1) {
    int e = blockIdx.z;
    int cnt = g_count[e];
    int m0 = blockIdx.x * BM;
    if (m0 >= cnt) return;
    int n0 = blockIdx.y * BN;

    __shared__ float As[BK][BM];
    __shared__ float Bs[BK][BN];
    __shared__ int sa[BM];

    int tid = threadIdx.x;
    if (tid < BM) sa[tid] = (m0 + tid < cnt) ? g_list[e * Tv + m0 + tid] : -1;
    __syncthreads();

    int tr = tid >> 4, tc = tid & 15;
    float acc[8][4];
#pragma unroll
    for (int i = 0; i < 8; i++)
#pragma unroll
        for (int j = 0; j < 4; j++) acc[i][j] = 0.f;

    int lr = tid >> 1;            // A-load row 0..127
    int lc = (tid & 1) * 8;       // A-load col 0 or 8
    int a_row = sa[lr];
    const float* aptr = (a_row >= 0) ? (x + (size_t)(a_row >> 1) * Dv + lc) : 0;

    int bk = tid >> 4;            // B-load k 0..15
    int bn = (tid & 15) * 4;      // B-load n
    const float* bbase = W1 + (size_t)e * Dv * Hv + n0 + bn;

    for (int k0 = 0; k0 < Dv; k0 += BK) {
        float4 a0v = make_float4(0.f, 0.f, 0.f, 0.f), a1v = a0v;
        if (aptr) {
            const float4* p = (const float4*)(aptr + k0);
            a0v = p[0]; a1v = p[1];
        }
        float4 bv = *(const float4*)(bbase + (size_t)(k0 + bk) * Hv);
        As[lc + 0][lr] = a0v.x; As[lc + 1][lr] = a0v.y;
        As[lc + 2][lr] = a0v.z; As[lc + 3][lr] = a0v.w;
        As[lc + 4][lr] = a1v.x; As[lc + 5][lr] = a1v.y;
        As[lc + 6][lr] = a1v.z; As[lc + 7][lr] = a1v.w;
        *(float4*)&Bs[bk][bn] = bv;
        __syncthreads();
#pragma unroll
        for (int kk = 0; kk < BK; kk++) {
            float rm[8], rn[4];
            *(float4*)&rm[0] = *(const float4*)&As[kk][tr * 8];
            *(float4*)&rm[4] = *(const float4*)&As[kk][tr * 8 + 4];
            *(float4*)&rn[0] = *(const float4*)&Bs[kk][tc * 4];
#pragma unroll
            for (int i = 0; i < 8; i++)
#pragma unroll
                for (int j = 0; j < 4; j++)
                    acc[i][j] = fmaf(rm[i], rn[j], acc[i][j]);
        }
        __syncthreads();
    }

    int n = n0 + tc * 4;
    const float* b1r = b1 + (size_t)e * Hv + n;
#pragma unroll
    for (int i = 0; i < 8; i++) {
        int r = tr * 8 + i;
        int a = sa[r];
        if (a < 0) continue;
        float4 o;
        o.x = gelu_tanh(acc[i][0] + b1r[0]);
        o.y = gelu_tanh(acc[i][1] + b1r[1]);
        o.z = gelu_tanh(acc[i][2] + b1r[2]);
        o.w = gelu_tanh(acc[i][3] + b1r[3]);
        *(float4*)&g_h[(size_t)a * Hv + n] = o;
    }
}

// FFN2: y[a, :] = w[a] * (h[a, :] @ W2[e]) for a in expert e's list
__global__ __launch_bounds__(256) void k_ffn2(const float* __restrict__ W2) {
    int e = blockIdx.z;
    int cnt = g_count[e];
    int m0 = blockIdx.x * BM;
    if (m0 >= cnt) return;
    int n0 = blockIdx.y * BN;

    __shared__ float As[BK][BM];
    __shared__ float Bs[BK][BN];
    __shared__ int sa[BM];

    int tid = threadIdx.x;
    if (tid < BM) sa[tid] = (m0 + tid < cnt) ? g_list[e * Tv + m0 + tid] : -1;
    __syncthreads();

    int tr = tid >> 4, tc = tid & 15;
    float acc[8][4];
#pragma unroll
    for (int i = 0; i < 8; i++)
#pragma unroll
        for (int j = 0; j < 4; j++) acc[i][j] = 0.f;

    int lr = tid >> 1;
    int lc = (tid & 1) * 8;
    int a_row = sa[lr];
    const float* aptr = (a_row >= 0) ? (g_h + (size_t)a_row * Hv + lc) : 0;

    int bk = tid >> 4;
    int bn = (tid & 15) * 4;
    const float* bbase = W2 + (size_t)e * Hv * Dv + n0 + bn;

    for (int k0 = 0; k0 < Hv; k0 += BK) {
        float4 a0v = make_float4(0.f, 0.f, 0.f, 0.f), a1v = a0v;
        if (aptr) {
            const float4* p = (const float4*)(aptr + k0);
            a0v = p[0]; a1v = p[1];
        }
        float4 bv = *(const float4*)(bbase + (size_t)(k0 + bk) * Dv);
        As[lc + 0][lr] = a0v.x; As[lc + 1][lr] = a0v.y;
        As[lc + 2][lr] = a0v.z; As[lc + 3][lr] = a0v.w;
        As[lc + 4][lr] = a1v.x; As[lc + 5][lr] = a1v.y;
        As[lc + 6][lr] = a1v.z; As[lc + 7][lr] = a1v.w;
        *(float4*)&Bs[bk][bn] = bv;
        __syncthreads();
#pragma unroll
        for (int kk = 0; kk < BK; kk++) {
            float rm[8], rn[4];
            *(float4*)&rm[0] = *(const float4*)&As[kk][tr * 8];
            *(float4*)&rm[4] = *(const float4*)&As[kk][tr * 8 + 4];
            *(float4*)&rn[0] = *(const float4*)&Bs[kk][tc * 4];
#pragma unroll
            for (int i = 0; i < 8; i++)
#pragma unroll
                for (int j = 0; j < 4; j++)
                    acc[i][j] = fmaf(rm[i], rn[j], acc[i][j]);
        }
        __syncthreads();
    }

    int n = n0 + tc * 4;
#pragma unroll
    for (int i = 0; i < 8; i++) {
        int r = tr * 8 + i;
        int a = sa[r];
        if (a < 0) continue;
        float w = g_w[a];
        float4 o;
        o.x = w * acc[i][0];
        o.y = w * acc[i][1];
        o.z = w * acc[i][2];
        o.w = w * acc[i][3];
        *(float4*)&g_y[(size_t)a * Dv + n] = o;
    }
}

// Combine: out[t] = y[2t] + y[2t+1] + w0*b2[e0] + w1*b2[e1]
__global__ void k_comb(const float* __restrict__ b2, float* __restrict__ out) {
    int idx = blockIdx.x * blockDim.x + threadIdx.x;   // over T*D/4
    int t = idx / (Dv / 4);
    int c = idx % (Dv / 4);
    int e0 = g_exp[2 * t], e1 = g_exp[2 * t + 1];
    float w0 = g_w[2 * t], w1 = g_w[2 * t + 1];
    float4 y0 = *(const float4*)&g_y[(size_t)(2 * t) * Dv + c * 4];
    float4 y1 = *(const float4*)&g_y[(size_t)(2 * t + 1) * Dv + c * 4];
    float4 bb0 = *(const float4*)&b2[(size_t)e0 * Dv + c * 4];
    float4 bb1 = *(const float4*)&b2[(size_t)e1 * Dv + c * 4];
    float4 o;
    o.x = y0.x + y1.x + w0 * bb0.x + w1 * bb1.x;
    o.y = y0.y + y1.y + w0 * bb0.y + w1 * bb1.y;
    o.z = y0.z + y1.z + w0 * bb0.z + w1 * bb1.z;
    o.w = y0.w + y1.w + w0 * bb0.w + w1 * bb1.w;
    *(float4*)&out[(size_t)t * Dv + c * 4] = o;
}

extern "C" void kernel_launch(void* const* d_in, const int* in_sizes, int n_in,
                              void* d_out, int out_size) {
    const float* x = (const float*)d_in[0];
    // top_k may or may not be materialized as a (size-1) input; detect it.
    int base = (n_in >= 8 && in_sizes[1] == 1) ? 2 : 1;
    const float* Wg = (const float*)d_in[base + 0];
    const float* bg = (const float*)d_in[base + 1];
    const float* W1 = (const float*)d_in[base + 2];
    const float* b1 = (const float*)d_in[base + 3];
    const float* W2 = (const float*)d_in[base + 4];
    const float* b2 = (const float*)d_in[base + 5];

    k_zero<<<1, 32>>>();
    k_gate<<<Tv / 8, 256>>>(x, Wg, bg);
    k_ffn1<<<dim3(Tv / BM, Hv / BN, Ev), 256>>>(x, W1, b1);
    k_ffn2<<<dim3(Tv / BM, Dv / BN, Ev), 256>>>(W2);
    k_comb<<<(Tv * Dv / 4) / 256, 256>>>(b2, (float*)d_out);
}

// round 6
// speedup vs baseline: 1.7218x; 1.7218x over previous
#include <cuda_runtime.h>
#include <math.h>

// Problem constants
#define Bv 4
#define Sv 2048
#define Dv 1024
#define Ev 8
#define Hv 2048
#define Tv (Bv*Sv)        // 8192 tokens
#define Av (2*Tv)         // 16384 assignments (top_k = 2)

// GEMM tiling
#define BM 128
#define BN 64
#define BK 32
#define LDA (BM + 8)
#define LDB (BN + 8)

// Device scratch (static allocations; no cudaMalloc allowed)
__device__ int   g_count[Ev];
__device__ int   g_list[Ev*Tv];           // assignment ids per expert
__device__ int   g_exp[Av];               // expert per assignment
__device__ float g_w[Av];                 // combine weight per assignment
__device__ float g_h[(size_t)Av*Hv];      // gelu(FFN1) activations, 134 MB
__device__ float g_y[(size_t)Av*Dv];      // weighted FFN2 outputs, 67 MB

__global__ void k_zero() {
    if (threadIdx.x < Ev) g_count[threadIdx.x] = 0;
}

// Gating: one warp per token. logits = x @ Wg + bg; top-2; normalized weights.
__global__ void k_gate(const float* __restrict__ x,
                       const float* __restrict__ Wg,
                       const float* __restrict__ bg) {
    int warp = threadIdx.x >> 5, lane = threadIdx.x & 31;
    int t = blockIdx.x * 8 + warp;
    if (t >= Tv) return;
    float acc[Ev];
#pragma unroll
    for (int e = 0; e < Ev; e++) acc[e] = 0.f;
    const float* xr = x + (size_t)t * Dv;
    for (int d = lane; d < Dv; d += 32) {
        float xv = xr[d];
        const float* wr = Wg + d * Ev;
#pragma unroll
        for (int e = 0; e < Ev; e++) acc[e] += xv * __ldg(wr + e);
    }
#pragma unroll
    for (int e = 0; e < Ev; e++) {
#pragma unroll
        for (int o = 16; o > 0; o >>= 1)
            acc[e] += __shfl_xor_sync(0xffffffffu, acc[e], o);
    }
    if (lane == 0) {
        float l[Ev];
#pragma unroll
        for (int e = 0; e < Ev; e++) l[e] = acc[e] + bg[e];
        int e0 = 0;
#pragma unroll
        for (int e = 1; e < Ev; e++) if (l[e] > l[e0]) e0 = e;
        int e1 = (e0 == 0) ? 1 : 0;
#pragma unroll
        for (int e = 0; e < Ev; e++) if (e != e0 && l[e] > l[e1]) e1 = e;
        float w0 = 1.f / (1.f + expf(l[e1] - l[e0]));
        float w1 = 1.f - w0;
        int a0 = 2 * t, a1 = 2 * t + 1;
        g_exp[a0] = e0; g_exp[a1] = e1;
        g_w[a0] = w0;   g_w[a1] = w1;
        int s0 = atomicAdd(&g_count[e0], 1); g_list[e0 * Tv + s0] = a0;
        int s1 = atomicAdd(&g_count[e1], 1); g_list[e1 * Tv + s1] = a1;
    }
}

__device__ __forceinline__ float gelu_tanh(float v) {
    float u = 0.7978845608028654f * (v + 0.044715f * v * v * v);
    float th;
    asm("tanh.approx.f32 %0, %1;" : "=f"(th) : "f"(u));
    return 0.5f * v * (1.f + th);
}

__device__ __forceinline__ unsigned f2tf(float f) {
    unsigned u;
    asm("cvt.rna.tf32.f32 %0, %1;" : "=r"(u) : "f"(f));
    return u;
}

__device__ __forceinline__ void mma_tf32(float c[4], const unsigned a[4], const unsigned b[2]) {
    asm volatile(
        "mma.sync.aligned.m16n8k8.row.col.f32.tf32.tf32.f32 "
        "{%0,%1,%2,%3}, {%4,%5,%6,%7}, {%8,%9}, {%0,%1,%2,%3};"
        : "+f"(c[0]), "+f"(c[1]), "+f"(c[2]), "+f"(c[3])
        : "r"(a[0]), "r"(a[1]), "r"(a[2]), "r"(a[3]), "r"(b[0]), "r"(b[1]));
}

// Shared GEMM core: computes C = gathered_A @ B for one 128x64 block tile.
// MODE 0: FFN1 (A = x rows, epilogue = gelu(+b1) -> g_h)
// MODE 1: FFN2 (A = g_h rows [device symbol], epilogue = w * acc -> g_y)
template <int MODE>
__global__ __launch_bounds__(256) void k_ffn_mma(const float* __restrict__ Asrc,
                                                 const float* __restrict__ Bsrc,
                                                 const float* __restrict__ bias) {
    const int Kdim = (MODE == 0) ? Dv : Hv;
    const int Ndim = (MODE == 0) ? Hv : Dv;
    // CRITICAL: __device__ arrays must be referenced from device code, never
    // passed as host-side launch arguments.
    const float* Aeff = (MODE == 0) ? Asrc : (const float*)g_h;

    int e = blockIdx.z;
    int cnt = g_count[e];
    int m0 = blockIdx.x * BM;
    if (m0 >= cnt) return;
    int n0 = blockIdx.y * BN;

    __shared__ unsigned As[BK][LDA];
    __shared__ unsigned Bs[BK][LDB];
    __shared__ int sa[BM];

    int tid = threadIdx.x;
    if (tid < BM) sa[tid] = (m0 + tid < cnt) ? g_list[e * Tv + m0 + tid] : -1;
    __syncthreads();

    int warp = tid >> 5, lane = tid & 31;
    int wm = (warp >> 2) * 64;        // warp m-offset within tile (0 or 64)
    int wn = (warp & 3) * 16;         // warp n-offset within tile (0..48)
    int g = lane >> 2, t = lane & 3;

    float c[4][2][4];
#pragma unroll
    for (int mt = 0; mt < 4; mt++)
#pragma unroll
        for (int nt = 0; nt < 2; nt++)
#pragma unroll
            for (int i = 0; i < 4; i++) c[mt][nt][i] = 0.f;

    // A gather setup: each thread loads 16 consecutive k for one row
    int lr = tid >> 1;                // row 0..127
    int lc = (tid & 1) * 16;          // k offset 0 or 16
    int a_row = sa[lr];
    const float* aptr = 0;
    if (a_row >= 0) {
        int src_row = (MODE == 0) ? (a_row >> 1) : a_row;   // token vs assignment
        aptr = Aeff + (size_t)src_row * Kdim + lc;
    }

    // B load setup: each thread loads 8 consecutive n for one k-row
    int bk = tid >> 3;                // k 0..31
    int bn = (tid & 7) * 8;           // n 0..56
    const float* bbase = Bsrc + (size_t)e * Kdim * Ndim + n0 + bn;

    for (int k0 = 0; k0 < Kdim; k0 += BK) {
        // Load A tile (gathered rows), convert to tf32, store transposed
        float4 a0v = make_float4(0.f, 0.f, 0.f, 0.f);
        float4 a1v = a0v, a2v = a0v, a3v = a0v;
        if (aptr) {
            const float4* p = (const float4*)(aptr + k0);
            a0v = p[0]; a1v = p[1]; a2v = p[2]; a3v = p[3];
        }
        // Load B tile
        const float* bp = bbase + (size_t)(k0 + bk) * Ndim;
        float4 b0v = *(const float4*)(bp);
        float4 b1v = *(const float4*)(bp + 4);

        As[lc + 0][lr] = f2tf(a0v.x);  As[lc + 1][lr] = f2tf(a0v.y);
        As[lc + 2][lr] = f2tf(a0v.z);  As[lc + 3][lr] = f2tf(a0v.w);
        As[lc + 4][lr] = f2tf(a1v.x);  As[lc + 5][lr] = f2tf(a1v.y);
        As[lc + 6][lr] = f2tf(a1v.z);  As[lc + 7][lr] = f2tf(a1v.w);
        As[lc + 8][lr] = f2tf(a2v.x);  As[lc + 9][lr] = f2tf(a2v.y);
        As[lc +10][lr] = f2tf(a2v.z);  As[lc +11][lr] = f2tf(a2v.w);
        As[lc +12][lr] = f2tf(a3v.x);  As[lc +13][lr] = f2tf(a3v.y);
        As[lc +14][lr] = f2tf(a3v.z);  As[lc +15][lr] = f2tf(a3v.w);

        Bs[bk][bn + 0] = f2tf(b0v.x);  Bs[bk][bn + 1] = f2tf(b0v.y);
        Bs[bk][bn + 2] = f2tf(b0v.z);  Bs[bk][bn + 3] = f2tf(b0v.w);
        Bs[bk][bn + 4] = f2tf(b1v.x);  Bs[bk][bn + 5] = f2tf(b1v.y);
        Bs[bk][bn + 6] = f2tf(b1v.z);  Bs[bk][bn + 7] = f2tf(b1v.w);
        __syncthreads();

#pragma unroll
        for (int ks = 0; ks < 4; ks++) {
            int kk = ks * 8;
            unsigned af[4][4], bf[2][2];
#pragma unroll
            for (int mt = 0; mt < 4; mt++) {
                int m = wm + mt * 16 + g;
                af[mt][0] = As[kk + t][m];
                af[mt][1] = As[kk + t][m + 8];
                af[mt][2] = As[kk + t + 4][m];
                af[mt][3] = As[kk + t + 4][m + 8];
            }
#pragma unroll
            for (int nt = 0; nt < 2; nt++) {
                int n = wn + nt * 8 + g;
                bf[nt][0] = Bs[kk + t][n];
                bf[nt][1] = Bs[kk + t + 4][n];
            }
#pragma unroll
            for (int mt = 0; mt < 4; mt++)
#pragma unroll
                for (int nt = 0; nt < 2; nt++)
                    mma_tf32(c[mt][nt], af[mt], bf[nt]);
        }
        __syncthreads();
    }

    // Epilogue
#pragma unroll
    for (int mt = 0; mt < 4; mt++) {
#pragma unroll
        for (int i = 0; i < 2; i++) {
            int row = wm + mt * 16 + g + i * 8;
            int a = sa[row];
            if (a < 0) continue;
            if (MODE == 0) {
#pragma unroll
                for (int nt = 0; nt < 2; nt++) {
                    int col = n0 + wn + nt * 8 + t * 2;
                    const float* br = bias + (size_t)e * Hv + col;
                    float2 o;
                    o.x = gelu_tanh(c[mt][nt][i * 2 + 0] + br[0]);
                    o.y = gelu_tanh(c[mt][nt][i * 2 + 1] + br[1]);
                    *(float2*)&g_h[(size_t)a * Hv + col] = o;
                }
            } else {
                float w = g_w[a];
#pragma unroll
                for (int nt = 0; nt < 2; nt++) {
                    int col = n0 + wn + nt * 8 + t * 2;
                    float2 o;
                    o.x = w * c[mt][nt][i * 2 + 0];
                    o.y = w * c[mt][nt][i * 2 + 1];
                    *(float2*)&g_y[(size_t)a * Dv + col] = o;
                }
            }
        }
    }
}

// Combine: out[t] = y[2t] + y[2t+1] + w0*b2[e0] + w1*b2[e1]
__global__ void k_comb(const float* __restrict__ b2, float* __restrict__ out) {
    int idx = blockIdx.x * blockDim.x + threadIdx.x;   // over T*D/4
    int t = idx / (Dv / 4);
    int c = idx % (Dv / 4);
    int e0 = g_exp[2 * t], e1 = g_exp[2 * t + 1];
    float w0 = g_w[2 * t], w1 = g_w[2 * t + 1];
    float4 y0 = *(const float4*)&g_y[(size_t)(2 * t) * Dv + c * 4];
    float4 y1 = *(const float4*)&g_y[(size_t)(2 * t + 1) * Dv + c * 4];
    float4 bb0 = *(const float4*)&b2[(size_t)e0 * Dv + c * 4];
    float4 bb1 = *(const float4*)&b2[(size_t)e1 * Dv + c * 4];
    float4 o;
    o.x = y0.x + y1.x + w0 * bb0.x + w1 * bb1.x;
    o.y = y0.y + y1.y + w0 * bb0.y + w1 * bb1.y;
    o.z = y0.z + y1.z + w0 * bb0.z + w1 * bb1.z;
    o.w = y0.w + y1.w + w0 * bb0.w + w1 * bb1.w;
    *(float4*)&out[(size_t)t * Dv + c * 4] = o;
}

extern "C" void kernel_launch(void* const* d_in, const int* in_sizes, int n_in,
                              void* d_out, int out_size) {
    const float* x = (const float*)d_in[0];
    int base = (n_in >= 8 && in_sizes[1] == 1) ? 2 : 1;
    const float* Wg = (const float*)d_in[base + 0];
    const float* bg = (const float*)d_in[base + 1];
    const float* W1 = (const float*)d_in[base + 2];
    const float* b1 = (const float*)d_in[base + 3];
    const float* W2 = (const float*)d_in[base + 4];
    const float* b2 = (const float*)d_in[base + 5];

    k_zero<<<1, 32>>>();
    k_gate<<<Tv / 8, 256>>>(x, Wg, bg);
    k_ffn_mma<0><<<dim3(Tv / BM, Hv / BN, Ev), 256>>>(x, W1, b1);
    k_ffn_mma<1><<<dim3(Tv / BM, Dv / BN, Ev), 256>>>(x /*ignored*/, W2, b1);
    k_comb<<<(Tv * Dv / 4) / 256, 256>>>(b2, (float*)d_out);
}

// round 7
// speedup vs baseline: 2.8964x; 1.6822x over previous
#include <cuda_runtime.h>
#include <math.h>

// Problem constants
#define Bv 4
#define Sv 2048
#define Dv 1024
#define Ev 8
#define Hv 2048
#define Tv (Bv*Sv)        // 8192 tokens
#define Av (2*Tv)         // 16384 assignments (top_k = 2)

// GEMM tiling
#define BM 128
#define BN 128
#define BK 32
#define LDAW 36           // words per A row (144B, 16B-aligned, conflict-free)
#define LDBW 136          // words per B row

// Device scratch (static allocations; no cudaMalloc allowed)
__device__ int   g_count[Ev];
__device__ int   g_list[Ev*Tv];           // assignment ids per expert
__device__ int   g_exp[Av];               // expert per assignment
__device__ float g_w[Av];                 // combine weight per assignment
__device__ float g_h[(size_t)Av*Hv];      // gelu(FFN1) activations, 134 MB
__device__ float g_y[(size_t)Av*Dv];      // weighted FFN2 outputs, 67 MB

__global__ void k_zero() {
    if (threadIdx.x < Ev) g_count[threadIdx.x] = 0;
}

// Gating: one warp per token. logits = x @ Wg + bg; top-2; normalized weights.
__global__ void k_gate(const float* __restrict__ x,
                       const float* __restrict__ Wg,
                       const float* __restrict__ bg) {
    int warp = threadIdx.x >> 5, lane = threadIdx.x & 31;
    int t = blockIdx.x * 8 + warp;
    if (t >= Tv) return;
    float acc[Ev];
#pragma unroll
    for (int e = 0; e < Ev; e++) acc[e] = 0.f;
    const float* xr = x + (size_t)t * Dv;
    for (int d = lane; d < Dv; d += 32) {
        float xv = xr[d];
        const float* wr = Wg + d * Ev;
#pragma unroll
        for (int e = 0; e < Ev; e++) acc[e] += xv * __ldg(wr + e);
    }
#pragma unroll
    for (int e = 0; e < Ev; e++) {
#pragma unroll
        for (int o = 16; o > 0; o >>= 1)
            acc[e] += __shfl_xor_sync(0xffffffffu, acc[e], o);
    }
    if (lane == 0) {
        float l[Ev];
#pragma unroll
        for (int e = 0; e < Ev; e++) l[e] = acc[e] + bg[e];
        int e0 = 0;
#pragma unroll
        for (int e = 1; e < Ev; e++) if (l[e] > l[e0]) e0 = e;
        int e1 = (e0 == 0) ? 1 : 0;
#pragma unroll
        for (int e = 0; e < Ev; e++) if (e != e0 && l[e] > l[e1]) e1 = e;
        float w0 = 1.f / (1.f + expf(l[e1] - l[e0]));
        float w1 = 1.f - w0;
        int a0 = 2 * t, a1 = 2 * t + 1;
        g_exp[a0] = e0; g_exp[a1] = e1;
        g_w[a0] = w0;   g_w[a1] = w1;
        int s0 = atomicAdd(&g_count[e0], 1); g_list[e0 * Tv + s0] = a0;
        int s1 = atomicAdd(&g_count[e1], 1); g_list[e1 * Tv + s1] = a1;
    }
}

__device__ __forceinline__ float gelu_tanh(float v) {
    float u = 0.7978845608028654f * (v + 0.044715f * v * v * v);
    float th;
    asm("tanh.approx.f32 %0, %1;" : "=f"(th) : "f"(u));
    return 0.5f * v * (1.f + th);
}

__device__ __forceinline__ unsigned f2tf(float f) {
    unsigned u;
    asm("cvt.rna.tf32.f32 %0, %1;" : "=r"(u) : "f"(f));
    return u;
}

__device__ __forceinline__ void mma_tf32(float c[4], const unsigned a[4], const unsigned b[2]) {
    asm volatile(
        "mma.sync.aligned.m16n8k8.row.col.f32.tf32.tf32.f32 "
        "{%0,%1,%2,%3}, {%4,%5,%6,%7}, {%8,%9}, {%0,%1,%2,%3};"
        : "+f"(c[0]), "+f"(c[1]), "+f"(c[2]), "+f"(c[3])
        : "r"(a[0]), "r"(a[1]), "r"(a[2]), "r"(a[3]), "r"(b[0]), "r"(b[1]));
}

// ldmatrix x4 on row-major 32-bit data: yields exactly the tf32 m16n8k8 A frag
__device__ __forceinline__ void ldsm_x4(unsigned r[4], unsigned addr) {
    asm volatile("ldmatrix.sync.aligned.m8n8.x4.shared.b16 {%0,%1,%2,%3}, [%4];"
                 : "=r"(r[0]), "=r"(r[1]), "=r"(r[2]), "=r"(r[3]) : "r"(addr));
}

// Grouped gather-GEMM 128x128 tile.
// MODE 0: FFN1 (A = x rows, epilogue = gelu(+b1) -> g_h)
// MODE 1: FFN2 (A = g_h rows [device symbol], epilogue = w * acc -> g_y)
template <int MODE>
__global__ __launch_bounds__(256, 2) void k_ffn_mma(const float* __restrict__ Asrc,
                                                    const float* __restrict__ Bsrc,
                                                    const float* __restrict__ bias) {
    const int Kdim = (MODE == 0) ? Dv : Hv;
    const int Ndim = (MODE == 0) ? Hv : Dv;
    const float* Aeff = (MODE == 0) ? Asrc : (const float*)g_h;

    int e = blockIdx.z;
    int cnt = g_count[e];
    int m0 = blockIdx.x * BM;
    if (m0 >= cnt) return;
    int n0 = blockIdx.y * BN;

    __shared__ unsigned As[BM][LDAW];   // row-major [m][k], 18432 B
    __shared__ unsigned Bs[BK][LDBW];   // [k][n], 17408 B
    __shared__ int sa[BM];

    int tid = threadIdx.x;
    if (tid < BM) sa[tid] = (m0 + tid < cnt) ? g_list[e * Tv + m0 + tid] : -1;
    __syncthreads();

    // ---- loader indices ----
    int ar = tid >> 3;            // A row base (0..31), rows ar+32p
    int ak = (tid & 7) * 4;       // A k offset (0..28)
    const float* aptr[4];
#pragma unroll
    for (int p = 0; p < 4; p++) {
        int r = ar + 32 * p;
        int a = sa[r];
        if (a >= 0) {
            int sr = (MODE == 0) ? (a >> 1) : a;    // token vs assignment row
            aptr[p] = Aeff + (size_t)sr * Kdim + ak;
        } else aptr[p] = 0;
    }
    int bn = (tid & 31) * 4;      // B n offset (lanes consecutive -> coalesced, conflict-free)
    int bkr = tid >> 5;           // B k row base (0..7), rows bkr+8p
    const float* bbase = Bsrc + (size_t)e * Kdim * Ndim + n0 + bn;

    // ---- fragment indices ----
    int warp = tid >> 5, lane = tid & 31;
    int wm = (warp >> 2) * 64;    // 0 or 64
    int wn = (warp & 3) * 32;     // 0,32,64,96
    int g = lane >> 2, t = lane & 3;
    // ldmatrix per-lane source row / k-add
    int lrow = (lane & 7) + ((lane >> 3) & 1) * 8;   // 0..15
    int lkadd = (lane >> 4) * 4;                     // 0 or 4
    unsigned asmem = (unsigned)__cvta_generic_to_shared(&As[0][0]);
    unsigned aFragBase = asmem + ((wm + lrow) * LDAW + lkadd) * 4;

    float c[4][4][4];
#pragma unroll
    for (int mt = 0; mt < 4; mt++)
#pragma unroll
        for (int nt = 0; nt < 4; nt++)
#pragma unroll
            for (int i = 0; i < 4; i++) c[mt][nt][i] = 0.f;

    for (int k0 = 0; k0 < Kdim; k0 += BK) {
        // A: gathered rows -> tf32 -> [m][k] row-major (STS.128, conflict-free)
#pragma unroll
        for (int p = 0; p < 4; p++) {
            float4 v = make_float4(0.f, 0.f, 0.f, 0.f);
            if (aptr[p]) v = *(const float4*)(aptr[p] + k0);
            uint4 u;
            u.x = f2tf(v.x); u.y = f2tf(v.y); u.z = f2tf(v.z); u.w = f2tf(v.w);
            *(uint4*)&As[ar + 32 * p][ak] = u;
        }
        // B: [k][n] coalesced (STS.128, conflict-free)
#pragma unroll
        for (int p = 0; p < 4; p++) {
            int bk = bkr + 8 * p;
            float4 v = *(const float4*)(bbase + (size_t)(k0 + bk) * Ndim);
            uint4 u;
            u.x = f2tf(v.x); u.y = f2tf(v.y); u.z = f2tf(v.z); u.w = f2tf(v.w);
            *(uint4*)&Bs[bk][bn] = u;
        }
        __syncthreads();

#pragma unroll
        for (int ks = 0; ks < 4; ks++) {
            int kk = ks * 8;
            unsigned af[4][4];
#pragma unroll
            for (int mt = 0; mt < 4; mt++)
                ldsm_x4(af[mt], aFragBase + (mt * 16 * LDAW + kk) * 4);
            unsigned bf[4][2];
#pragma unroll
            for (int nt = 0; nt < 4; nt++) {
                int n = wn + nt * 8 + g;
                bf[nt][0] = Bs[kk + t][n];
                bf[nt][1] = Bs[kk + t + 4][n];
            }
#pragma unroll
            for (int mt = 0; mt < 4; mt++)
#pragma unroll
                for (int nt = 0; nt < 4; nt++)
                    mma_tf32(c[mt][nt], af[mt], bf[nt]);
        }
        __syncthreads();
    }

    // Epilogue
#pragma unroll
    for (int mt = 0; mt < 4; mt++) {
#pragma unroll
        for (int i = 0; i < 2; i++) {
            int row = wm + mt * 16 + g + i * 8;
            int a = sa[row];
            if (a < 0) continue;
            if (MODE == 0) {
#pragma unroll
                for (int nt = 0; nt < 4; nt++) {
                    int col = n0 + wn + nt * 8 + t * 2;
                    const float* br = bias + (size_t)e * Hv + col;
                    float2 o;
                    o.x = gelu_tanh(c[mt][nt][i * 2 + 0] + br[0]);
                    o.y = gelu_tanh(c[mt][nt][i * 2 + 1] + br[1]);
                    *(float2*)&g_h[(size_t)a * Hv + col] = o;
                }
            } else {
                float w = g_w[a];
#pragma unroll
                for (int nt = 0; nt < 4; nt++) {
                    int col = n0 + wn + nt * 8 + t * 2;
                    float2 o;
                    o.x = w * c[mt][nt][i * 2 + 0];
                    o.y = w * c[mt][nt][i * 2 + 1];
                    *(float2*)&g_y[(size_t)a * Dv + col] = o;
                }
            }
        }
    }
}

// Combine: out[t] = y[2t] + y[2t+1] + w0*b2[e0] + w1*b2[e1]
__global__ void k_comb(const float* __restrict__ b2, float* __restrict__ out) {
    int idx = blockIdx.x * blockDim.x + threadIdx.x;   // over T*D/4
    int t = idx / (Dv / 4);
    int c = idx % (Dv / 4);
    int e0 = g_exp[2 * t], e1 = g_exp[2 * t + 1];
    float w0 = g_w[2 * t], w1 = g_w[2 * t + 1];
    float4 y0 = *(const float4*)&g_y[(size_t)(2 * t) * Dv + c * 4];
    float4 y1 = *(const float4*)&g_y[(size_t)(2 * t + 1) * Dv + c * 4];
    float4 bb0 = *(const float4*)&b2[(size_t)e0 * Dv + c * 4];
    float4 bb1 = *(const float4*)&b2[(size_t)e1 * Dv + c * 4];
    float4 o;
    o.x = y0.x + y1.x + w0 * bb0.x + w1 * bb1.x;
    o.y = y0.y + y1.y + w0 * bb0.y + w1 * bb1.y;
    o.z = y0.z + y1.z + w0 * bb0.z + w1 * bb1.z;
    o.w = y0.w + y1.w + w0 * bb0.w + w1 * bb1.w;
    *(float4*)&out[(size_t)t * Dv + c * 4] = o;
}

extern "C" void kernel_launch(void* const* d_in, const int* in_sizes, int n_in,
                              void* d_out, int out_size) {
    const float* x = (const float*)d_in[0];
    int base = (n_in >= 8 && in_sizes[1] == 1) ? 2 : 1;
    const float* Wg = (const float*)d_in[base + 0];
    const float* bg = (const float*)d_in[base + 1];
    const float* W1 = (const float*)d_in[base + 2];
    const float* b1 = (const float*)d_in[base + 3];
    const float* W2 = (const float*)d_in[base + 4];
    const float* b2 = (const float*)d_in[base + 5];

    k_zero<<<1, 32>>>();
    k_gate<<<Tv / 8, 256>>>(x, Wg, bg);
    k_ffn_mma<0><<<dim3(Tv / BM, Hv / BN, Ev), 256>>>(x, W1, b1);
    k_ffn_mma<1><<<dim3(Tv / BM, Dv / BN, Ev), 256>>>(x /*ignored*/, W2, b1);
    k_comb<<<(Tv * Dv / 4) / 256, 256>>>(b2, (float*)d_out);
}

// round 8
// speedup vs baseline: 3.2319x; 1.1159x over previous
#include <cuda_runtime.h>
#include <math.h>

// Problem constants
#define Bv 4
#define Sv 2048
#define Dv 1024
#define Ev 8
#define Hv 2048
#define Tv (Bv*Sv)        // 8192 tokens
#define Av (2*Tv)         // 16384 assignments (top_k = 2)

// GEMM tiling
#define BM 128
#define BN 128
#define BK 32
#define LDAW 36           // words per A row (144B, 16B-aligned, conflict-free)
#define LDBW 136          // words per B row (mod 32 == 8 -> conflict-free frag LDS)

#define STAGE_A_BYTES (BM*LDAW*4)              // 18432
#define STAGE_B_BYTES (BK*LDBW*4)              // 17408
#define STAGE_BYTES   (STAGE_A_BYTES + STAGE_B_BYTES)  // 35840
#define SMEM_TOTAL    (2*STAGE_BYTES)          // 71680

// Device scratch (static allocations; no cudaMalloc allowed)
__device__ int   g_count[Ev];
__device__ int   g_list[Ev*Tv];           // assignment ids per expert
__device__ int   g_exp[Av];               // expert per assignment
__device__ float g_w[Av];                 // combine weight per assignment
__device__ float g_h[(size_t)Av*Hv];      // gelu(FFN1) activations, 134 MB
__device__ float g_y[(size_t)Av*Dv];      // weighted FFN2 outputs, 67 MB

__global__ void k_zero() {
    if (threadIdx.x < Ev) g_count[threadIdx.x] = 0;
}

// Gating: one warp per token. logits = x @ Wg + bg; top-2; normalized weights.
__global__ void k_gate(const float* __restrict__ x,
                       const float* __restrict__ Wg,
                       const float* __restrict__ bg) {
    int warp = threadIdx.x >> 5, lane = threadIdx.x & 31;
    int t = blockIdx.x * 8 + warp;
    if (t >= Tv) return;
    float acc[Ev];
#pragma unroll
    for (int e = 0; e < Ev; e++) acc[e] = 0.f;
    const float* xr = x + (size_t)t * Dv;
    for (int d = lane; d < Dv; d += 32) {
        float xv = xr[d];
        const float* wr = Wg + d * Ev;
#pragma unroll
        for (int e = 0; e < Ev; e++) acc[e] += xv * __ldg(wr + e);
    }
#pragma unroll
    for (int e = 0; e < Ev; e++) {
#pragma unroll
        for (int o = 16; o > 0; o >>= 1)
            acc[e] += __shfl_xor_sync(0xffffffffu, acc[e], o);
    }
    if (lane == 0) {
        float l[Ev];
#pragma unroll
        for (int e = 0; e < Ev; e++) l[e] = acc[e] + bg[e];
        int e0 = 0;
#pragma unroll
        for (int e = 1; e < Ev; e++) if (l[e] > l[e0]) e0 = e;
        int e1 = (e0 == 0) ? 1 : 0;
#pragma unroll
        for (int e = 0; e < Ev; e++) if (e != e0 && l[e] > l[e1]) e1 = e;
        float w0 = 1.f / (1.f + expf(l[e1] - l[e0]));
        float w1 = 1.f - w0;
        int a0 = 2 * t, a1 = 2 * t + 1;
        g_exp[a0] = e0; g_exp[a1] = e1;
        g_w[a0] = w0;   g_w[a1] = w1;
        int s0 = atomicAdd(&g_count[e0], 1); g_list[e0 * Tv + s0] = a0;
        int s1 = atomicAdd(&g_count[e1], 1); g_list[e1 * Tv + s1] = a1;
    }
}

__device__ __forceinline__ float gelu_tanh(float v) {
    float u = 0.7978845608028654f * (v + 0.044715f * v * v * v);
    float th;
    asm("tanh.approx.f32 %0, %1;" : "=f"(th) : "f"(u));
    return 0.5f * v * (1.f + th);
}

__device__ __forceinline__ unsigned f2tf(unsigned raw) {
    unsigned u;
    asm("cvt.rna.tf32.f32 %0, %1;" : "=r"(u) : "f"(__uint_as_float(raw)));
    return u;
}

__device__ __forceinline__ void mma_tf32(float c[4], const unsigned a[4], const unsigned b[2]) {
    asm volatile(
        "mma.sync.aligned.m16n8k8.row.col.f32.tf32.tf32.f32 "
        "{%0,%1,%2,%3}, {%4,%5,%6,%7}, {%8,%9}, {%0,%1,%2,%3};"
        : "+f"(c[0]), "+f"(c[1]), "+f"(c[2]), "+f"(c[3])
        : "r"(a[0]), "r"(a[1]), "r"(a[2]), "r"(a[3]), "r"(b[0]), "r"(b[1]));
}

// ldmatrix x4 on row-major 32-bit data: yields exactly the tf32 m16n8k8 A frag
__device__ __forceinline__ void ldsm_x4(unsigned r[4], unsigned addr) {
    asm volatile("ldmatrix.sync.aligned.m8n8.x4.shared.b16 {%0,%1,%2,%3}, [%4];"
                 : "=r"(r[0]), "=r"(r[1]), "=r"(r[2]), "=r"(r[3]) : "r"(addr));
}

__device__ __forceinline__ void cp_async16(unsigned smem_addr, const void* gptr, int src_bytes) {
    asm volatile("cp.async.ca.shared.global [%0], [%1], 16, %2;"
                 :: "r"(smem_addr), "l"(gptr), "r"(src_bytes));
}
__device__ __forceinline__ void cp_commit() {
    asm volatile("cp.async.commit_group;");
}
__device__ __forceinline__ void cp_wait0() {
    asm volatile("cp.async.wait_group 0;");
}

// Grouped gather-GEMM 128x128 tile, 2-stage cp.async pipeline.
// MODE 0: FFN1 (A = x rows, epilogue = gelu(+b1) -> g_h)
// MODE 1: FFN2 (A = g_h rows [device symbol], epilogue = w * acc -> g_y)
template <int MODE>
__global__ __launch_bounds__(256, 2) void k_ffn_mma(const float* __restrict__ Asrc,
                                                    const float* __restrict__ Bsrc,
                                                    const float* __restrict__ bias) {
    const int Kdim = (MODE == 0) ? Dv : Hv;
    const int Ndim = (MODE == 0) ? Hv : Dv;
    const float* Aeff = (MODE == 0) ? Asrc : (const float*)g_h;

    extern __shared__ char dynsmem[];
    __shared__ int sa[BM];

    int e = blockIdx.z;
    int cnt = g_count[e];
    int m0 = blockIdx.x * BM;
    if (m0 >= cnt) return;
    int n0 = blockIdx.y * BN;

    int tid = threadIdx.x;
    if (tid < BM) sa[tid] = (m0 + tid < cnt) ? g_list[e * Tv + m0 + tid] : -1;
    __syncthreads();

    // ---- loader indices ----
    int ar = tid >> 3;            // A row base (0..31), rows ar+32p
    int ak = (tid & 7) * 4;       // A k offset (0..28)
    const float* aptr[4];
    int asz[4];
#pragma unroll
    for (int p = 0; p < 4; p++) {
        int r = ar + 32 * p;
        int a = sa[r];
        if (a >= 0) {
            int sr = (MODE == 0) ? (a >> 1) : a;    // token vs assignment row
            aptr[p] = Aeff + (size_t)sr * Kdim + ak;
            asz[p] = 16;
        } else { aptr[p] = Aeff; asz[p] = 0; }      // zero-fill, src unread
    }
    int bn = (tid & 31) * 4;      // B n offset (coalesced, conflict-free STS)
    int bkr = tid >> 5;           // B k row base (0..7), rows bkr+8p
    const float* bbase = Bsrc + (size_t)e * Kdim * Ndim + n0 + bn;

    unsigned smemBase = (unsigned)__cvta_generic_to_shared(dynsmem);
    // per-thread fixed smem store offsets within a stage
    unsigned aStoreOff[4];
#pragma unroll
    for (int p = 0; p < 4; p++) aStoreOff[p] = ((ar + 32 * p) * LDAW + ak) * 4;
    unsigned bStoreOff[4];
#pragma unroll
    for (int p = 0; p < 4; p++) bStoreOff[p] = STAGE_A_BYTES + ((bkr + 8 * p) * LDBW + bn) * 4;

    // ---- fragment indices ----
    int warp = tid >> 5, lane = tid & 31;
    int wm = (warp >> 2) * 64;    // 0 or 64
    int wn = (warp & 3) * 32;     // 0,32,64,96
    int g = lane >> 2, t = lane & 3;
    int lrow = (lane & 7) + ((lane >> 3) & 1) * 8;   // 0..15
    int lkadd = (lane >> 4) * 4;                     // 0 or 4
    unsigned aFragOff = ((wm + lrow) * LDAW + lkadd) * 4;

    float c[4][4][4];
#pragma unroll
    for (int mt = 0; mt < 4; mt++)
#pragma unroll
        for (int nt = 0; nt < 4; nt++)
#pragma unroll
            for (int i = 0; i < 4; i++) c[mt][nt][i] = 0.f;

    const int nslab = Kdim / BK;

    // prologue: issue stage 0
    {
        unsigned sb = smemBase;
#pragma unroll
        for (int p = 0; p < 4; p++) cp_async16(sb + aStoreOff[p], aptr[p], asz[p]);
#pragma unroll
        for (int p = 0; p < 4; p++)
            cp_async16(sb + bStoreOff[p], bbase + (size_t)(bkr + 8 * p) * Ndim, 16);
        cp_commit();
    }

    for (int i = 0; i < nslab; i++) {
        cp_wait0();
        __syncthreads();   // stage i ready; all warps done computing stage i-1

        // issue stage i+1 (overwrites buffer last computed at i-1; safe after sync)
        if (i + 1 < nslab) {
            int k0 = (i + 1) * BK;
            unsigned sb = smemBase + ((i + 1) & 1) * STAGE_BYTES;
#pragma unroll
            for (int p = 0; p < 4; p++) cp_async16(sb + aStoreOff[p], aptr[p] + k0, asz[p]);
#pragma unroll
            for (int p = 0; p < 4; p++)
                cp_async16(sb + bStoreOff[p], bbase + (size_t)(k0 + bkr + 8 * p) * Ndim, 16);
            cp_commit();
        }

        // compute on stage i
        unsigned sb = smemBase + (i & 1) * STAGE_BYTES;
        const unsigned* BsT = (const unsigned*)(dynsmem + (i & 1) * STAGE_BYTES + STAGE_A_BYTES);
#pragma unroll
        for (int ks = 0; ks < 4; ks++) {
            int kk = ks * 8;
            unsigned af[4][4];
#pragma unroll
            for (int mt = 0; mt < 4; mt++) {
                ldsm_x4(af[mt], sb + aFragOff + (mt * 16 * LDAW + kk) * 4);
#pragma unroll
                for (int j = 0; j < 4; j++) af[mt][j] = f2tf(af[mt][j]);
            }
            unsigned bf[4][2];
#pragma unroll
            for (int nt = 0; nt < 4; nt++) {
                int n = wn + nt * 8 + g;
                bf[nt][0] = f2tf(BsT[(kk + t) * LDBW + n]);
                bf[nt][1] = f2tf(BsT[(kk + t + 4) * LDBW + n]);
            }
#pragma unroll
            for (int mt = 0; mt < 4; mt++)
#pragma unroll
                for (int nt = 0; nt < 4; nt++)
                    mma_tf32(c[mt][nt], af[mt], bf[nt]);
        }
    }

    // Epilogue
#pragma unroll
    for (int mt = 0; mt < 4; mt++) {
#pragma unroll
        for (int i = 0; i < 2; i++) {
            int row = wm + mt * 16 + g + i * 8;
            int a = sa[row];
            if (a < 0) continue;
            if (MODE == 0) {
#pragma unroll
                for (int nt = 0; nt < 4; nt++) {
                    int col = n0 + wn + nt * 8 + t * 2;
                    const float* br = bias + (size_t)e * Hv + col;
                    float2 o;
                    o.x = gelu_tanh(c[mt][nt][i * 2 + 0] + br[0]);
                    o.y = gelu_tanh(c[mt][nt][i * 2 + 1] + br[1]);
                    *(float2*)&g_h[(size_t)a * Hv + col] = o;
                }
            } else {
                float w = g_w[a];
#pragma unroll
                for (int nt = 0; nt < 4; nt++) {
                    int col = n0 + wn + nt * 8 + t * 2;
                    float2 o;
                    o.x = w * c[mt][nt][i * 2 + 0];
                    o.y = w * c[mt][nt][i * 2 + 1];
                    *(float2*)&g_y[(size_t)a * Dv + col] = o;
                }
            }
        }
    }
}

// Combine: out[t] = y[2t] + y[2t+1] + w0*b2[e0] + w1*b2[e1]
__global__ void k_comb(const float* __restrict__ b2, float* __restrict__ out) {
    int idx = blockIdx.x * blockDim.x + threadIdx.x;   // over T*D/4
    int t = idx / (Dv / 4);
    int c = idx % (Dv / 4);
    int e0 = g_exp[2 * t], e1 = g_exp[2 * t + 1];
    float w0 = g_w[2 * t], w1 = g_w[2 * t + 1];
    float4 y0 = *(const float4*)&g_y[(size_t)(2 * t) * Dv + c * 4];
    float4 y1 = *(const float4*)&g_y[(size_t)(2 * t + 1) * Dv + c * 4];
    float4 bb0 = *(const float4*)&b2[(size_t)e0 * Dv + c * 4];
    float4 bb1 = *(const float4*)&b2[(size_t)e1 * Dv + c * 4];
    float4 o;
    o.x = y0.x + y1.x + w0 * bb0.x + w1 * bb1.x;
    o.y = y0.y + y1.y + w0 * bb0.y + w1 * bb1.y;
    o.z = y0.z + y1.z + w0 * bb0.z + w1 * bb1.z;
    o.w = y0.w + y1.w + w0 * bb0.w + w1 * bb1.w;
    *(float4*)&out[(size_t)t * Dv + c * 4] = o;
}

extern "C" void kernel_launch(void* const* d_in, const int* in_sizes, int n_in,
                              void* d_out, int out_size) {
    const float* x = (const float*)d_in[0];
    int base = (n_in >= 8 && in_sizes[1] == 1) ? 2 : 1;
    const float* Wg = (const float*)d_in[base + 0];
    const float* bg = (const float*)d_in[base + 1];
    const float* W1 = (const float*)d_in[base + 2];
    const float* b1 = (const float*)d_in[base + 3];
    const float* W2 = (const float*)d_in[base + 4];
    const float* b2 = (const float*)d_in[base + 5];

    cudaFuncSetAttribute(k_ffn_mma<0>, cudaFuncAttributeMaxDynamicSharedMemorySize, SMEM_TOTAL);
    cudaFuncSetAttribute(k_ffn_mma<1>, cudaFuncAttributeMaxDynamicSharedMemorySize, SMEM_TOTAL);

    k_zero<<<1, 32>>>();
    k_gate<<<Tv / 8, 256>>>(x, Wg, bg);
    k_ffn_mma<0><<<dim3(Tv / BM, Hv / BN, Ev), 256, SMEM_TOTAL>>>(x, W1, b1);
    k_ffn_mma<1><<<dim3(Tv / BM, Dv / BN, Ev), 256, SMEM_TOTAL>>>(x /*ignored*/, W2, b1);
    k_comb<<<(Tv * Dv / 4) / 256, 256>>>(b2, (float*)d_out);
}